// round 16
// baseline (speedup 1.0000x reference)
#include <cuda_runtime.h>
#include <cuda_fp16.h>
#include <cstdint>

// Problem constants
#define BATCH 8192
#define NFEAT 16
#define EMBD  32
#define VOCAB 100000
#define NDOM  8
#define HID1  1024
#define HID2  512
#define INDIM 512
#define EPS   1e-5f

// ---------------- scratch (device globals; no allocations allowed) ----------------
__device__ __half g_embh[(size_t)BATCH * INDIM];               // 8 MB
__device__ __half g_w1h[(size_t)NDOM * HID1 * INDIM];          // 8 MB
__device__ __half g_w2h[(size_t)NDOM * HID2 * HID1];           // 8 MB
__device__ __half g_h1h[(size_t)NDOM * BATCH * HID1];          // 128 MB
__device__ __half g_h2sel[(size_t)BATCH * HID2];               // 8 MB (domain-selected h2)
__device__ float g_sum1[NDOM * HID1];
__device__ float g_sq1 [NDOM * HID1];
__device__ float g_sum2[NDOM * HID2];
__device__ float g_sq2 [NDOM * HID2];

// ---------------- PTX helpers ----------------
__device__ __forceinline__ void mma_f16(float c[4], const uint32_t a[4], const uint32_t b[2]) {
    asm volatile(
        "mma.sync.aligned.m16n8k16.row.col.f32.f16.f16.f32 "
        "{%0,%1,%2,%3}, {%4,%5,%6,%7}, {%8,%9}, {%0,%1,%2,%3};\n"
        : "+f"(c[0]), "+f"(c[1]), "+f"(c[2]), "+f"(c[3])
        : "r"(a[0]), "r"(a[1]), "r"(a[2]), "r"(a[3]), "r"(b[0]), "r"(b[1]));
}
__device__ __forceinline__ void ldsm4(uint32_t& r0, uint32_t& r1, uint32_t& r2, uint32_t& r3,
                                      uint32_t addr) {
    asm volatile("ldmatrix.sync.aligned.m8n8.x4.shared.b16 {%0,%1,%2,%3}, [%4];"
                 : "=r"(r0), "=r"(r1), "=r"(r2), "=r"(r3) : "r"(addr));
}
__device__ __forceinline__ void cp16(uint32_t dst, const void* src) {
    asm volatile("cp.async.cg.shared.global [%0], [%1], 16;" :: "r"(dst), "l"(src));
}
__device__ __forceinline__ void cp_commit() { asm volatile("cp.async.commit_group;"); }
template <int N> __device__ __forceinline__ void cp_wait() {
    asm volatile("cp.async.wait_group %0;" :: "n"(N));
}
__device__ __forceinline__ uint32_t hfma2_relu(uint32_t a, uint32_t s, uint32_t b) {
    __half2 av = *(__half2*)&a, sv = *(__half2*)&s, bv = *(__half2*)&b;
    __half2 r = __hmax2(__hfma2(av, sv, bv), __half2(__float2half(0.f), __float2half(0.f)));
    return *(uint32_t*)&r;
}

// ---------------- prep: f2h W1 + f2h W2 + gather + stats-init, one launch ----------------
__global__ void prep_kernel(const float* __restrict__ W1, const float* __restrict__ W2,
                            const int* __restrict__ feat_ids, const float* __restrict__ tabs) {
    const int bx = blockIdx.x;
    const int tid = threadIdx.x;
    if (bx < 8192) {
        const float* src = (bx < 4096) ? W1 : W2;
        __half* dst = (bx < 4096) ? g_w1h : g_w2h;
        int bb = (bx < 4096) ? bx : bx - 4096;
        int i = (bb * 256 + tid) * 4;
        float4 v = *(const float4*)(src + i);
        __half2 h0 = __floats2half2_rn(v.x, v.y);
        __half2 h1 = __floats2half2_rn(v.z, v.w);
        uint2 u;
        u.x = *(uint32_t*)&h0;
        u.y = *(uint32_t*)&h1;
        *(uint2*)(dst + i) = u;
        return;
    }
    // gather blocks: 4096 blocks x 2 batch rows
    const int gb = bx - 8192;
    {   // stats init piggyback (first 64 blocks cover all stat floats)
        int i = gb * 256 + tid;
        if (i < NDOM * HID1) { g_sum1[i] = 0.f; g_sq1[i] = 0.f; }
        if (i < NDOM * HID2) { g_sum2[i] = 0.f; g_sq2[i] = 0.f; }
    }
    int b = gb * 2 + (tid >> 7);
    int t = tid & 127;
    int f = t >> 3, c4 = t & 7;
    int id = feat_ids[b * NFEAT + f];
    const float4 v = *(const float4*)(tabs + ((size_t)f * VOCAB + id) * EMBD + c4 * 4);
    __half2 h0 = __floats2half2_rn(v.x, v.y);
    __half2 h1 = __floats2half2_rn(v.z, v.w);
    uint2 u;
    u.x = *(uint32_t*)&h0;
    u.y = *(uint32_t*)&h1;
    *(uint2*)(g_embh + (size_t)b * INDIM + t * 4) = u;
}

// ---------------- final: BN2 + ReLU + dot(W3) + sigmoid, vectorized contiguous lanes ----------------
// One warp per sample. Lane owns k in [lane*16, lane*16+16): h2 via 4x uint2,
// each stats/W3 array via 4x float4 — 24 wide loads per lane vs 96 scalar.
__global__ void final_kernel(const int* __restrict__ domain_id,
                             const float* __restrict__ g2, const float* __restrict__ be2,
                             const float* __restrict__ W3, const float* __restrict__ b3,
                             float* __restrict__ out) {
    int b = blockIdx.x * (blockDim.x / 32) + (threadIdx.x >> 5);
    int lane = threadIdx.x & 31;
    if (b >= BATCH) return;
    int d = domain_id[b];
    const int k0 = lane * 16;
    const __half* h2 = g_h2sel + (size_t)b * HID2 + k0;
    const float* su = g_sum2 + d * HID2 + k0;
    const float* sq = g_sq2 + d * HID2 + k0;
    const float* ga = g2 + d * HID2 + k0;
    const float* be = be2 + d * HID2 + k0;
    const float* w3 = W3 + d * HID2 + k0;
    const float invB = 1.0f / (float)BATCH;
    float z = 0.f;
    #pragma unroll
    for (int c = 0; c < 4; c++) {
        uint2 hv = *(const uint2*)(h2 + c * 4);
        __half2 h01 = *(__half2*)&hv.x;
        __half2 h23 = *(__half2*)&hv.y;
        float hx[4];
        {
            float2 f01 = __half22float2(h01);
            float2 f23 = __half22float2(h23);
            hx[0] = f01.x; hx[1] = f01.y; hx[2] = f23.x; hx[3] = f23.y;
        }
        float4 suv = *(const float4*)(su + c * 4);
        float4 sqv = *(const float4*)(sq + c * 4);
        float4 gav = *(const float4*)(ga + c * 4);
        float4 bev = *(const float4*)(be + c * 4);
        float4 w3v = *(const float4*)(w3 + c * 4);
        const float* sup = &suv.x;
        const float* sqp = &sqv.x;
        const float* gap = &gav.x;
        const float* bep = &bev.x;
        const float* w3p = &w3v.x;
        #pragma unroll
        for (int q = 0; q < 4; q++) {
            float mean = sup[q] * invB;
            float var = sqp[q] * invB - mean * mean;
            float s = gap[q] * rsqrtf(var + EPS);
            float bb = bep[q] - mean * s;
            float x = fmaxf(fmaf(hx[q], s, bb), 0.f);
            z = fmaf(x, w3p[q], z);
        }
    }
    #pragma unroll
    for (int off = 16; off > 0; off >>= 1) z += __shfl_xor_sync(0xFFFFFFFFu, z, off);
    if (lane == 0) out[b] = 1.0f / (1.0f + expf(-(z + b3[d])));
}

// ---------------- fp16 GEMM (f32 acc), BM=128 BN=128, 4 warps (2x2), warp tile 64x64 ----------------
// (champion mainloop, frozen)
// BNRELU=false (GEMM1): full store of C[d,m,n].
// BNRELU=true  (GEMM2): BN1+ReLU on A frags (scale/bias derived in prologue),
//   domain-selective store into compact C0[m*NTOT+n] iff domain_id[m]==d.
//   Stats always accumulated over all (d, m).
template <int K, int NTOT, bool BNRELU>
__global__ __launch_bounds__(128, 2)
void gemm_h(const __half* __restrict__ A0, const __half* __restrict__ W0,
            __half* __restrict__ C0,
            const float* __restrict__ sumK, const float* __restrict__ sqK,
            const float* __restrict__ gK, const float* __restrict__ beK,
            const int* __restrict__ dom,
            float* __restrict__ sumN, float* __restrict__ sqN) {
    constexpr int BM = 128, BN = 128, BK = 64;
    constexpr uint32_t A_SZ = BM * BK * 2;   // 16 KB per stage
    constexpr uint32_t B_SZ = BN * BK * 2;   // 16 KB per stage
    constexpr int NT = K / BK;
    extern __shared__ char smem[];
    __shared__ __align__(16) __half s_sc[BNRELU ? K : 8];
    __shared__ __align__(16) __half s_bi[BNRELU ? K : 8];
    __shared__ int s_dom[BNRELU ? BM : 1];

    const int d = blockIdx.z;
    const int bm0 = blockIdx.x * BM;
    const int bn0 = blockIdx.y * BN;
    const __half* A = BNRELU ? (A0 + (size_t)d * BATCH * K) : A0;
    const __half* W = W0 + (size_t)d * NTOT * K + (size_t)bn0 * K;
    __half* C = BNRELU ? C0 : (C0 + (size_t)d * BATCH * NTOT);

    const int tid = threadIdx.x;
    const int lane = tid & 31;
    const int wid = tid >> 5;
    const int wm = wid & 1;    // 2 warps in M: 64 rows each
    const int wn = wid >> 1;   // 2 warps in N: 64 cols each

    const uint32_t s_base = (uint32_t)__cvta_generic_to_shared(smem);

    auto stage = [&](int t, int s) {
        const int kt = t * BK;
        const uint32_t ab = s_base + (uint32_t)s * A_SZ;
        const uint32_t bb = s_base + 2 * A_SZ + (uint32_t)s * B_SZ;
        #pragma unroll
        for (int i = 0; i < 8; i++) {          // A: 1024 x 16B chunks, 128 threads
            int idx = tid + i * 128;
            int r = idx >> 3, c = idx & 7;
            cp16(ab + (uint32_t)(r * 128 + ((c ^ (r & 7)) << 4)),
                 A + (size_t)(bm0 + r) * K + kt + c * 8);
        }
        #pragma unroll
        for (int i = 0; i < 8; i++) {          // B: 1024 x 16B chunks
            int idx = tid + i * 128;
            int r = idx >> 3, c = idx & 7;
            cp16(bb + (uint32_t)(r * 128 + ((c ^ (r & 7)) << 4)),
                 W + (size_t)r * K + kt + c * 8);
        }
    };

    stage(0, 0);
    cp_commit();

    // prologue fusion (overlaps in-flight tile-0 cp.async; published by t=0 barrier):
    if constexpr (BNRELU) {
        const float invB = 1.0f / (float)BATCH;
        #pragma unroll
        for (int k = tid; k < K; k += 128) {
            float mean = sumK[d * K + k] * invB;
            float var = sqK[d * K + k] * invB - mean * mean;
            float s = gK[d * K + k] * rsqrtf(var + EPS);
            float b = beK[d * K + k] - mean * s;
            s_sc[k] = __float2half(s);
            s_bi[k] = __float2half(b);
        }
        s_dom[tid] = dom[bm0 + tid];   // 128 threads, one row each
    }

    // ldmatrix per-thread addressing
    const int j = lane >> 3;
    const int i7 = lane & 7;
    uint32_t a_rowoff[4], a_swz[4];
    #pragma unroll
    for (int mt = 0; mt < 4; mt++) {
        int rA = wm * 64 + mt * 16 + (j & 1) * 8 + i7;
        a_rowoff[mt] = (uint32_t)(rA * 128);
        a_swz[mt] = (uint32_t)(rA & 7);
    }
    const int a_chi = j >> 1;
    uint32_t b_rowoff[4], b_swz[4];
    #pragma unroll
    for (int p = 0; p < 4; p++) {
        int rB = wn * 64 + p * 16 + (j >> 1) * 8 + i7;
        b_rowoff[p] = (uint32_t)(rB * 128);
        b_swz[p] = (uint32_t)(rB & 7);
    }
    const int b_chi = j & 1;

    float acc[4][8][4];
    #pragma unroll
    for (int i = 0; i < 4; i++)
        #pragma unroll
        for (int jj = 0; jj < 8; jj++)
            #pragma unroll
            for (int r = 0; r < 4; r++) acc[i][jj][r] = 0.f;

    for (int t = 0; t < NT; t++) {
        const int buf = t & 1;
        cp_wait<0>();               // tile t fully in smem (only group pending)
        __syncthreads();            // buffer buf^1 free; publishes s_sc/s_bi/s_dom at t=0

        if (t + 1 < NT) {
            stage(t + 1, buf ^ 1);  // overlaps entire compute of tile t
            cp_commit();
        }

        const uint32_t abase = s_base + (uint32_t)buf * A_SZ;
        const uint32_t bbase = s_base + 2 * A_SZ + (uint32_t)buf * B_SZ;
        const int kt = t * BK;

        #pragma unroll
        for (int kk = 0; kk < BK; kk += 16) {
            const uint32_t ck = (uint32_t)(kk >> 3);
            uint32_t afr[4][4], bfr[8][2];
            #pragma unroll
            for (int mt = 0; mt < 4; mt++) {
                uint32_t addr = abase + a_rowoff[mt] + (((ck + a_chi) ^ a_swz[mt]) << 4);
                ldsm4(afr[mt][0], afr[mt][1], afr[mt][2], afr[mt][3], addr);
            }
            #pragma unroll
            for (int p = 0; p < 4; p++) {
                uint32_t addr = bbase + b_rowoff[p] + (((ck + b_chi) ^ b_swz[p]) << 4);
                ldsm4(bfr[2 * p][0], bfr[2 * p][1], bfr[2 * p + 1][0], bfr[2 * p + 1][1], addr);
            }
            if constexpr (BNRELU) {
                const int kb = kt + kk + (lane & 3) * 2;
                uint32_t slo = *(const uint32_t*)(s_sc + kb);
                uint32_t shi = *(const uint32_t*)(s_sc + kb + 8);
                uint32_t olo = *(const uint32_t*)(s_bi + kb);
                uint32_t ohi = *(const uint32_t*)(s_bi + kb + 8);
                #pragma unroll
                for (int mt = 0; mt < 4; mt++) {
                    afr[mt][0] = hfma2_relu(afr[mt][0], slo, olo);
                    afr[mt][1] = hfma2_relu(afr[mt][1], slo, olo);
                    afr[mt][2] = hfma2_relu(afr[mt][2], shi, ohi);
                    afr[mt][3] = hfma2_relu(afr[mt][3], shi, ohi);
                }
            }
            #pragma unroll
            for (int mt = 0; mt < 4; mt++)
                #pragma unroll
                for (int nt = 0; nt < 8; nt++)
                    mma_f16(acc[mt][nt], afr[mt], bfr[nt]);
        }
    }

    // epilogue: store C (fp16; domain-selective for GEMM2) + fused per-column fp32 stats
    const int lr0 = wm * 64 + (lane >> 2);
    const int gc0 = bn0 + wn * 64 + (lane & 3) * 2;
    #pragma unroll
    for (int mt = 0; mt < 4; mt++) {
        const int lr = lr0 + mt * 16;
        bool st0 = true, st1 = true;
        if constexpr (BNRELU) {
            st0 = (s_dom[lr] == d);
            st1 = (s_dom[lr + 8] == d);
        }
        #pragma unroll
        for (int nt = 0; nt < 8; nt++) {
            int r = bm0 + lr, c = gc0 + nt * 8;
            if (st0)
                *(__half2*)(C + (size_t)r * NTOT + c) =
                    __floats2half2_rn(acc[mt][nt][0], acc[mt][nt][1]);
            if (st1)
                *(__half2*)(C + (size_t)(r + 8) * NTOT + c) =
                    __floats2half2_rn(acc[mt][nt][2], acc[mt][nt][3]);
        }
    }
    #pragma unroll
    for (int nt = 0; nt < 8; nt++) {
        float sA = 0.f, sB = 0.f, qA = 0.f, qB = 0.f;
        #pragma unroll
        for (int mt = 0; mt < 4; mt++) {
            float x0 = acc[mt][nt][0], x1 = acc[mt][nt][1];
            float x2 = acc[mt][nt][2], x3 = acc[mt][nt][3];
            sA += x0 + x2;  sB += x1 + x3;
            qA += x0 * x0 + x2 * x2;  qB += x1 * x1 + x3 * x3;
        }
        #pragma unroll
        for (int off = 4; off < 32; off <<= 1) {
            sA += __shfl_xor_sync(0xFFFFFFFFu, sA, off);
            sB += __shfl_xor_sync(0xFFFFFFFFu, sB, off);
            qA += __shfl_xor_sync(0xFFFFFFFFu, qA, off);
            qB += __shfl_xor_sync(0xFFFFFFFFu, qB, off);
        }
        if ((lane >> 2) == 0) {
            int c = gc0 + nt * 8;
            atomicAdd(&sumN[d * NTOT + c],     sA);
            atomicAdd(&sumN[d * NTOT + c + 1], sB);
            atomicAdd(&sqN [d * NTOT + c],     qA);
            atomicAdd(&sqN [d * NTOT + c + 1], qB);
        }
    }
}

// ---------------- launch ----------------
extern "C" void kernel_launch(void* const* d_in, const int* in_sizes, int n_in,
                              void* d_out, int out_size) {
    (void)in_sizes; (void)n_in; (void)out_size;
    const int*   feat_ids  = (const int*)d_in[0];
    const int*   domain_id = (const int*)d_in[1];
    const float* emb_tabs  = (const float*)d_in[2];
    const float* W1        = (const float*)d_in[3];
    // d_in[4] = b1: cancels under BatchNorm
    const float* g1        = (const float*)d_in[5];
    const float* be1       = (const float*)d_in[6];
    const float* W2        = (const float*)d_in[7];
    // d_in[8] = b2: cancels under BatchNorm
    const float* g2        = (const float*)d_in[9];
    const float* be2       = (const float*)d_in[10];
    const float* W3        = (const float*)d_in[11];
    const float* b3        = (const float*)d_in[12];
    float* out = (float*)d_out;

    __half *embh, *w1h, *w2h, *h1h, *h2sel;
    float *sum1, *sq1, *sum2, *sq2;
    cudaGetSymbolAddress((void**)&embh,  g_embh);
    cudaGetSymbolAddress((void**)&w1h,   g_w1h);
    cudaGetSymbolAddress((void**)&w2h,   g_w2h);
    cudaGetSymbolAddress((void**)&h1h,   g_h1h);
    cudaGetSymbolAddress((void**)&h2sel, g_h2sel);
    cudaGetSymbolAddress((void**)&sum1,  g_sum1);
    cudaGetSymbolAddress((void**)&sq1,   g_sq1);
    cudaGetSymbolAddress((void**)&sum2,  g_sum2);
    cudaGetSymbolAddress((void**)&sq2,   g_sq2);

    const int SMEM_BYTES = 2 * (128 * 64 * 2 + 128 * 64 * 2);  // 64 KB dynamic
    cudaFuncSetAttribute(gemm_h<INDIM, HID1, false>,
                         cudaFuncAttributeMaxDynamicSharedMemorySize, SMEM_BYTES);
    cudaFuncSetAttribute(gemm_h<HID1, HID2, true>,
                         cudaFuncAttributeMaxDynamicSharedMemorySize, SMEM_BYTES);

    // 1: prep (f2h W1 + f2h W2 + gather + stats-init), one wide launch
    prep_kernel<<<12288, 256>>>(W1, W2, feat_ids, emb_tabs);

    // 2: GEMM1: [8192,512] x [1024,512]^T per domain -> h1 (full) + stats
    gemm_h<INDIM, HID1, false><<<dim3(BATCH / 128, HID1 / 128, NDOM), 128, SMEM_BYTES>>>(
        embh, w1h, h1h, nullptr, nullptr, nullptr, nullptr, nullptr, sum1, sq1);

    // 3: GEMM2 (fused BN1 finalize; domain-selective store): -> h2sel [B,512] + stats
    gemm_h<HID1, HID2, true><<<dim3(BATCH / 128, HID2 / 128, NDOM), 128, SMEM_BYTES>>>(
        h1h, w2h, h2sel, sum1, sq1, g1, be1, domain_id, sum2, sq2);

    // 4: final (fused BN2 finalize, vectorized): BN2+ReLU+dot(W3)+sigmoid on h2sel
    final_kernel<<<BATCH / 8, 256>>>(domain_id, g2, be2, W3, b3, out);
}

// round 17
// speedup vs baseline: 1.0233x; 1.0233x over previous
#include <cuda_runtime.h>
#include <cuda_fp16.h>
#include <cstdint>

// Problem constants
#define BATCH 8192
#define NFEAT 16
#define EMBD  32
#define VOCAB 100000
#define NDOM  8
#define HID1  1024
#define HID2  512
#define INDIM 512
#define EPS   1e-5f

// ---------------- scratch (device globals; no allocations allowed) ----------------
__device__ __half g_embh[(size_t)BATCH * INDIM];               // 8 MB
__device__ __half g_w1h[(size_t)NDOM * HID1 * INDIM];          // 8 MB
__device__ __half g_w2h[(size_t)NDOM * HID2 * HID1];           // 8 MB
__device__ __half g_h1h[(size_t)NDOM * BATCH * HID1];          // 128 MB
__device__ __half g_h2sel[(size_t)BATCH * HID2];               // 8 MB (domain-selected h2)
__device__ float g_sum1[NDOM * HID1];
__device__ float g_sq1 [NDOM * HID1];
__device__ float g_sum2[NDOM * HID2];
__device__ float g_sq2 [NDOM * HID2];

// ---------------- PTX helpers ----------------
__device__ __forceinline__ void mma_f16(float c[4], const uint32_t a[4], const uint32_t b[2]) {
    asm volatile(
        "mma.sync.aligned.m16n8k16.row.col.f32.f16.f16.f32 "
        "{%0,%1,%2,%3}, {%4,%5,%6,%7}, {%8,%9}, {%0,%1,%2,%3};\n"
        : "+f"(c[0]), "+f"(c[1]), "+f"(c[2]), "+f"(c[3])
        : "r"(a[0]), "r"(a[1]), "r"(a[2]), "r"(a[3]), "r"(b[0]), "r"(b[1]));
}
__device__ __forceinline__ void ldsm4(uint32_t& r0, uint32_t& r1, uint32_t& r2, uint32_t& r3,
                                      uint32_t addr) {
    asm volatile("ldmatrix.sync.aligned.m8n8.x4.shared.b16 {%0,%1,%2,%3}, [%4];"
                 : "=r"(r0), "=r"(r1), "=r"(r2), "=r"(r3) : "r"(addr));
}
__device__ __forceinline__ void cp16(uint32_t dst, const void* src) {
    asm volatile("cp.async.cg.shared.global [%0], [%1], 16;" :: "r"(dst), "l"(src));
}
__device__ __forceinline__ void cp_commit() { asm volatile("cp.async.commit_group;"); }
template <int N> __device__ __forceinline__ void cp_wait() {
    asm volatile("cp.async.wait_group %0;" :: "n"(N));
}
__device__ __forceinline__ uint32_t hfma2_relu(uint32_t a, uint32_t s, uint32_t b) {
    __half2 av = *(__half2*)&a, sv = *(__half2*)&s, bv = *(__half2*)&b;
    __half2 r = __hmax2(__hfma2(av, sv, bv), __half2(__float2half(0.f), __float2half(0.f)));
    return *(uint32_t*)&r;
}

// ---------------- prep: f2h W1 + f2h W2 + gather + stats-init, one launch ----------------
__global__ void prep_kernel(const float* __restrict__ W1, const float* __restrict__ W2,
                            const int* __restrict__ feat_ids, const float* __restrict__ tabs) {
    const int bx = blockIdx.x;
    const int tid = threadIdx.x;
    if (bx < 8192) {
        const float* src = (bx < 4096) ? W1 : W2;
        __half* dst = (bx < 4096) ? g_w1h : g_w2h;
        int bb = (bx < 4096) ? bx : bx - 4096;
        int i = (bb * 256 + tid) * 4;
        float4 v = *(const float4*)(src + i);
        __half2 h0 = __floats2half2_rn(v.x, v.y);
        __half2 h1 = __floats2half2_rn(v.z, v.w);
        uint2 u;
        u.x = *(uint32_t*)&h0;
        u.y = *(uint32_t*)&h1;
        *(uint2*)(dst + i) = u;
        return;
    }
    // gather blocks: 4096 blocks x 2 batch rows
    const int gb = bx - 8192;
    {   // stats init piggyback (first 64 blocks cover all stat floats)
        int i = gb * 256 + tid;
        if (i < NDOM * HID1) { g_sum1[i] = 0.f; g_sq1[i] = 0.f; }
        if (i < NDOM * HID2) { g_sum2[i] = 0.f; g_sq2[i] = 0.f; }
    }
    int b = gb * 2 + (tid >> 7);
    int t = tid & 127;
    int f = t >> 3, c4 = t & 7;
    int id = feat_ids[b * NFEAT + f];
    const float4 v = *(const float4*)(tabs + ((size_t)f * VOCAB + id) * EMBD + c4 * 4);
    __half2 h0 = __floats2half2_rn(v.x, v.y);
    __half2 h1 = __floats2half2_rn(v.z, v.w);
    uint2 u;
    u.x = *(uint32_t*)&h0;
    u.y = *(uint32_t*)&h1;
    *(uint2*)(g_embh + (size_t)b * INDIM + t * 4) = u;
}

// ---------------- final: on-the-fly BN2 + ReLU + dot(W3) + sigmoid (R15 scalar-coalesced) ----------------
__global__ void final_kernel(const int* __restrict__ domain_id,
                             const float* __restrict__ g2, const float* __restrict__ be2,
                             const float* __restrict__ W3, const float* __restrict__ b3,
                             float* __restrict__ out) {
    int b = blockIdx.x * (blockDim.x / 32) + (threadIdx.x >> 5);
    int lane = threadIdx.x & 31;
    if (b >= BATCH) return;
    int d = domain_id[b];
    const __half* h2 = g_h2sel + (size_t)b * HID2;
    const float* su = g_sum2 + d * HID2;
    const float* sq = g_sq2 + d * HID2;
    const float* ga = g2 + d * HID2;
    const float* be = be2 + d * HID2;
    const float* w3 = W3 + d * HID2;
    const float invB = 1.0f / (float)BATCH;
    float z = 0.f;
    #pragma unroll
    for (int k = lane; k < HID2; k += 32) {
        float mean = su[k] * invB;
        float var = sq[k] * invB - mean * mean;
        float s = ga[k] * rsqrtf(var + EPS);
        float bb = be[k] - mean * s;
        float x = fmaxf(fmaf(__half2float(h2[k]), s, bb), 0.f);
        z = fmaf(x, w3[k], z);
    }
    #pragma unroll
    for (int off = 16; off > 0; off >>= 1) z += __shfl_xor_sync(0xFFFFFFFFu, z, off);
    if (lane == 0) out[b] = 1.0f / (1.0f + expf(-(z + b3[d])));
}

// ---------------- fp16 GEMM (f32 acc), BM=128 BN=128, 4 warps (2x2), warp tile 64x64 ----------------
// (champion mainloop, frozen)
// BNRELU=false (GEMM1): grid (m, n, d), full store of C[d,m,n].
// BNRELU=true  (GEMM2): grid (n, m, d) — n fastest so the 4 CTAs sharing an A-tile
//   run adjacently (A-tile: 1 DRAM fetch + 3 L2 hits). BN1+ReLU on A frags
//   (scale/bias derived in prologue), domain-selective store into compact
//   C0[m*NTOT+n] iff domain_id[m]==d. Stats accumulated over all (d, m).
template <int K, int NTOT, bool BNRELU>
__global__ __launch_bounds__(128, 2)
void gemm_h(const __half* __restrict__ A0, const __half* __restrict__ W0,
            __half* __restrict__ C0,
            const float* __restrict__ sumK, const float* __restrict__ sqK,
            const float* __restrict__ gK, const float* __restrict__ beK,
            const int* __restrict__ dom,
            float* __restrict__ sumN, float* __restrict__ sqN) {
    constexpr int BM = 128, BN = 128, BK = 64;
    constexpr uint32_t A_SZ = BM * BK * 2;   // 16 KB per stage
    constexpr uint32_t B_SZ = BN * BK * 2;   // 16 KB per stage
    constexpr int NT = K / BK;
    extern __shared__ char smem[];
    __shared__ __align__(16) __half s_sc[BNRELU ? K : 8];
    __shared__ __align__(16) __half s_bi[BNRELU ? K : 8];
    __shared__ int s_dom[BNRELU ? BM : 1];

    const int d = blockIdx.z;
    const int bm0 = (BNRELU ? blockIdx.y : blockIdx.x) * BM;
    const int bn0 = (BNRELU ? blockIdx.x : blockIdx.y) * BN;
    const __half* A = BNRELU ? (A0 + (size_t)d * BATCH * K) : A0;
    const __half* W = W0 + (size_t)d * NTOT * K + (size_t)bn0 * K;
    __half* C = BNRELU ? C0 : (C0 + (size_t)d * BATCH * NTOT);

    const int tid = threadIdx.x;
    const int lane = tid & 31;
    const int wid = tid >> 5;
    const int wm = wid & 1;    // 2 warps in M: 64 rows each
    const int wn = wid >> 1;   // 2 warps in N: 64 cols each

    const uint32_t s_base = (uint32_t)__cvta_generic_to_shared(smem);

    auto stage = [&](int t, int s) {
        const int kt = t * BK;
        const uint32_t ab = s_base + (uint32_t)s * A_SZ;
        const uint32_t bb = s_base + 2 * A_SZ + (uint32_t)s * B_SZ;
        #pragma unroll
        for (int i = 0; i < 8; i++) {          // A: 1024 x 16B chunks, 128 threads
            int idx = tid + i * 128;
            int r = idx >> 3, c = idx & 7;
            cp16(ab + (uint32_t)(r * 128 + ((c ^ (r & 7)) << 4)),
                 A + (size_t)(bm0 + r) * K + kt + c * 8);
        }
        #pragma unroll
        for (int i = 0; i < 8; i++) {          // B: 1024 x 16B chunks
            int idx = tid + i * 128;
            int r = idx >> 3, c = idx & 7;
            cp16(bb + (uint32_t)(r * 128 + ((c ^ (r & 7)) << 4)),
                 W + (size_t)r * K + kt + c * 8);
        }
    };

    stage(0, 0);
    cp_commit();

    // prologue fusion (overlaps in-flight tile-0 cp.async; published by t=0 barrier):
    if constexpr (BNRELU) {
        const float invB = 1.0f / (float)BATCH;
        #pragma unroll
        for (int k = tid; k < K; k += 128) {
            float mean = sumK[d * K + k] * invB;
            float var = sqK[d * K + k] * invB - mean * mean;
            float s = gK[d * K + k] * rsqrtf(var + EPS);
            float b = beK[d * K + k] - mean * s;
            s_sc[k] = __float2half(s);
            s_bi[k] = __float2half(b);
        }
        s_dom[tid] = dom[bm0 + tid];   // 128 threads, one row each
    }

    // ldmatrix per-thread addressing
    const int j = lane >> 3;
    const int i7 = lane & 7;
    uint32_t a_rowoff[4], a_swz[4];
    #pragma unroll
    for (int mt = 0; mt < 4; mt++) {
        int rA = wm * 64 + mt * 16 + (j & 1) * 8 + i7;
        a_rowoff[mt] = (uint32_t)(rA * 128);
        a_swz[mt] = (uint32_t)(rA & 7);
    }
    const int a_chi = j >> 1;
    uint32_t b_rowoff[4], b_swz[4];
    #pragma unroll
    for (int p = 0; p < 4; p++) {
        int rB = wn * 64 + p * 16 + (j >> 1) * 8 + i7;
        b_rowoff[p] = (uint32_t)(rB * 128);
        b_swz[p] = (uint32_t)(rB & 7);
    }
    const int b_chi = j & 1;

    float acc[4][8][4];
    #pragma unroll
    for (int i = 0; i < 4; i++)
        #pragma unroll
        for (int jj = 0; jj < 8; jj++)
            #pragma unroll
            for (int r = 0; r < 4; r++) acc[i][jj][r] = 0.f;

    for (int t = 0; t < NT; t++) {
        const int buf = t & 1;
        cp_wait<0>();               // tile t fully in smem (only group pending)
        __syncthreads();            // buffer buf^1 free; publishes s_sc/s_bi/s_dom at t=0

        if (t + 1 < NT) {
            stage(t + 1, buf ^ 1);  // overlaps entire compute of tile t
            cp_commit();
        }

        const uint32_t abase = s_base + (uint32_t)buf * A_SZ;
        const uint32_t bbase = s_base + 2 * A_SZ + (uint32_t)buf * B_SZ;
        const int kt = t * BK;

        #pragma unroll
        for (int kk = 0; kk < BK; kk += 16) {
            const uint32_t ck = (uint32_t)(kk >> 3);
            uint32_t afr[4][4], bfr[8][2];
            #pragma unroll
            for (int mt = 0; mt < 4; mt++) {
                uint32_t addr = abase + a_rowoff[mt] + (((ck + a_chi) ^ a_swz[mt]) << 4);
                ldsm4(afr[mt][0], afr[mt][1], afr[mt][2], afr[mt][3], addr);
            }
            #pragma unroll
            for (int p = 0; p < 4; p++) {
                uint32_t addr = bbase + b_rowoff[p] + (((ck + b_chi) ^ b_swz[p]) << 4);
                ldsm4(bfr[2 * p][0], bfr[2 * p][1], bfr[2 * p + 1][0], bfr[2 * p + 1][1], addr);
            }
            if constexpr (BNRELU) {
                const int kb = kt + kk + (lane & 3) * 2;
                uint32_t slo = *(const uint32_t*)(s_sc + kb);
                uint32_t shi = *(const uint32_t*)(s_sc + kb + 8);
                uint32_t olo = *(const uint32_t*)(s_bi + kb);
                uint32_t ohi = *(const uint32_t*)(s_bi + kb + 8);
                #pragma unroll
                for (int mt = 0; mt < 4; mt++) {
                    afr[mt][0] = hfma2_relu(afr[mt][0], slo, olo);
                    afr[mt][1] = hfma2_relu(afr[mt][1], slo, olo);
                    afr[mt][2] = hfma2_relu(afr[mt][2], shi, ohi);
                    afr[mt][3] = hfma2_relu(afr[mt][3], shi, ohi);
                }
            }
            #pragma unroll
            for (int mt = 0; mt < 4; mt++)
                #pragma unroll
                for (int nt = 0; nt < 8; nt++)
                    mma_f16(acc[mt][nt], afr[mt], bfr[nt]);
        }
    }

    // epilogue: store C (fp16; domain-selective for GEMM2) + fused per-column fp32 stats
    const int lr0 = wm * 64 + (lane >> 2);
    const int gc0 = bn0 + wn * 64 + (lane & 3) * 2;
    #pragma unroll
    for (int mt = 0; mt < 4; mt++) {
        const int lr = lr0 + mt * 16;
        bool st0 = true, st1 = true;
        if constexpr (BNRELU) {
            st0 = (s_dom[lr] == d);
            st1 = (s_dom[lr + 8] == d);
        }
        #pragma unroll
        for (int nt = 0; nt < 8; nt++) {
            int r = bm0 + lr, c = gc0 + nt * 8;
            if (st0)
                *(__half2*)(C + (size_t)r * NTOT + c) =
                    __floats2half2_rn(acc[mt][nt][0], acc[mt][nt][1]);
            if (st1)
                *(__half2*)(C + (size_t)(r + 8) * NTOT + c) =
                    __floats2half2_rn(acc[mt][nt][2], acc[mt][nt][3]);
        }
    }
    #pragma unroll
    for (int nt = 0; nt < 8; nt++) {
        float sA = 0.f, sB = 0.f, qA = 0.f, qB = 0.f;
        #pragma unroll
        for (int mt = 0; mt < 4; mt++) {
            float x0 = acc[mt][nt][0], x1 = acc[mt][nt][1];
            float x2 = acc[mt][nt][2], x3 = acc[mt][nt][3];
            sA += x0 + x2;  sB += x1 + x3;
            qA += x0 * x0 + x2 * x2;  qB += x1 * x1 + x3 * x3;
        }
        #pragma unroll
        for (int off = 4; off < 32; off <<= 1) {
            sA += __shfl_xor_sync(0xFFFFFFFFu, sA, off);
            sB += __shfl_xor_sync(0xFFFFFFFFu, sB, off);
            qA += __shfl_xor_sync(0xFFFFFFFFu, qA, off);
            qB += __shfl_xor_sync(0xFFFFFFFFu, qB, off);
        }
        if ((lane >> 2) == 0) {
            int c = gc0 + nt * 8;
            atomicAdd(&sumN[d * NTOT + c],     sA);
            atomicAdd(&sumN[d * NTOT + c + 1], sB);
            atomicAdd(&sqN [d * NTOT + c],     qA);
            atomicAdd(&sqN [d * NTOT + c + 1], qB);
        }
    }
}

// ---------------- launch ----------------
extern "C" void kernel_launch(void* const* d_in, const int* in_sizes, int n_in,
                              void* d_out, int out_size) {
    (void)in_sizes; (void)n_in; (void)out_size;
    const int*   feat_ids  = (const int*)d_in[0];
    const int*   domain_id = (const int*)d_in[1];
    const float* emb_tabs  = (const float*)d_in[2];
    const float* W1        = (const float*)d_in[3];
    // d_in[4] = b1: cancels under BatchNorm
    const float* g1        = (const float*)d_in[5];
    const float* be1       = (const float*)d_in[6];
    const float* W2        = (const float*)d_in[7];
    // d_in[8] = b2: cancels under BatchNorm
    const float* g2        = (const float*)d_in[9];
    const float* be2       = (const float*)d_in[10];
    const float* W3        = (const float*)d_in[11];
    const float* b3        = (const float*)d_in[12];
    float* out = (float*)d_out;

    __half *embh, *w1h, *w2h, *h1h, *h2sel;
    float *sum1, *sq1, *sum2, *sq2;
    cudaGetSymbolAddress((void**)&embh,  g_embh);
    cudaGetSymbolAddress((void**)&w1h,   g_w1h);
    cudaGetSymbolAddress((void**)&w2h,   g_w2h);
    cudaGetSymbolAddress((void**)&h1h,   g_h1h);
    cudaGetSymbolAddress((void**)&h2sel, g_h2sel);
    cudaGetSymbolAddress((void**)&sum1,  g_sum1);
    cudaGetSymbolAddress((void**)&sq1,   g_sq1);
    cudaGetSymbolAddress((void**)&sum2,  g_sum2);
    cudaGetSymbolAddress((void**)&sq2,   g_sq2);

    const int SMEM_BYTES = 2 * (128 * 64 * 2 + 128 * 64 * 2);  // 64 KB dynamic
    cudaFuncSetAttribute(gemm_h<INDIM, HID1, false>,
                         cudaFuncAttributeMaxDynamicSharedMemorySize, SMEM_BYTES);
    cudaFuncSetAttribute(gemm_h<HID1, HID2, true>,
                         cudaFuncAttributeMaxDynamicSharedMemorySize, SMEM_BYTES);

    // 1: prep (f2h W1 + f2h W2 + gather + stats-init), one wide launch
    prep_kernel<<<12288, 256>>>(W1, W2, feat_ids, emb_tabs);

    // 2: GEMM1: grid (m, n, d) -> h1 (full) + stats
    gemm_h<INDIM, HID1, false><<<dim3(BATCH / 128, HID1 / 128, NDOM), 128, SMEM_BYTES>>>(
        embh, w1h, h1h, nullptr, nullptr, nullptr, nullptr, nullptr, sum1, sq1);

    // 3: GEMM2: grid (n, m, d) — n fastest for A-tile L2 reuse; fused BN1 finalize;
    //    domain-selective store -> h2sel [B,512] + stats
    gemm_h<HID1, HID2, true><<<dim3(HID2 / 128, BATCH / 128, NDOM), 128, SMEM_BYTES>>>(
        h1h, w2h, h2sel, sum1, sq1, g1, be1, domain_id, sum2, sq2);

    // 4: final (fused BN2 finalize, scalar-coalesced): BN2+ReLU+dot(W3)+sigmoid on h2sel
    final_kernel<<<BATCH / 8, 256>>>(domain_id, g2, be2, W3, b3, out);
}